// round 11
// baseline (speedup 1.0000x reference)
#include <cuda_runtime.h>
#include <cuda_fp16.h>
#include <math.h>

#define B 64
#define T 256
#define F 64
#define H 1024
#define G4H 4096
#define NCTA 128
#define NTHR 512

typedef unsigned long long ull;
typedef unsigned int u32;

// ---------------- scratch globals ----------------
__device__ __align__(256) float g_xg[(size_t)T * G4H * B];   // [T][4096][B]
__device__ __align__(256) float g_actA[(size_t)T * H * B];   // [T][H][B]
__device__ __align__(256) float g_actB[(size_t)T * H * B];   // [T][H][B]
// fp16 fragment images: entry (kc, mt, lane) -> 16B
__device__ __align__(256) unsigned char g_hImg[2][64 * 4 * 32 * 16];          // h image (128KB each)
__device__ __align__(256) unsigned char g_xImg[(size_t)T * 64 * 4 * 32 * 16]; // x image, K=1024 layers
__device__ __align__(256) unsigned char g_x1Img[(size_t)T * 4 * 4 * 32 * 16]; // x image, K=64 layer 1
// hierarchical barrier state (monotonic counters; no resets)
__device__ __align__(256) unsigned g_grp[8][64];   // one counter per 256B line
__device__ __align__(256) unsigned g_root[64];
__device__ __align__(256) unsigned g_gen;

// ---------------- helpers ----------------
__device__ __forceinline__ float sigf(float x) {
    return __fdividef(1.f, 1.f + __expf(-x));
}
// inf-safe fast tanh: 1 - 2/(e^{2x}+1);  x->-inf: e->0 -> -1;  x->+inf: e->inf -> 1.
__device__ __forceinline__ float tanhf_fast(float x) {
    return 1.f - __fdividef(2.f, __expf(2.f * x) + 1.f);
}

__device__ __forceinline__ u32 packhf(float a, float b) {
    __half2 h = __floats2half2_rn(a, b);
    return *(u32*)&h;
}

__device__ __forceinline__ void mma_f16(float* d, const uint4& a, u32 b0, u32 b1) {
    asm volatile(
        "mma.sync.aligned.m16n8k16.row.col.f32.f16.f16.f32 "
        "{%0,%1,%2,%3},{%4,%5,%6,%7},{%8,%9},{%0,%1,%2,%3};"
        : "+f"(d[0]), "+f"(d[1]), "+f"(d[2]), "+f"(d[3])
        : "r"(a.x), "r"(a.y), "r"(a.z), "r"(a.w), "r"(b0), "r"(b1));
}

__device__ __forceinline__ u32 ioff(int kc, int mt, int lane) {
    return (u32)(((kc * 4 + mt) * 32 + lane) << 4);
}
template <bool CG>
__device__ __forceinline__ uint4 ldimg(const unsigned char* img, int kc, int mt, int lane) {
    const uint4* p = (const uint4*)(img + ioff(kc, mt, lane));
    return CG ? __ldcg(p) : __ldg(p);
}

// Hierarchical grid barrier (proven R10): 16-way group -> 8-way root -> g_gen.
// Single polling thread per CTA. target = per-launch base + t + 1; wrap-safe.
__device__ __forceinline__ void grid_barrier_h(unsigned target, int tid, int cb) {
    __syncthreads();
    if (tid == 0) {
        __threadfence();                       // release: publish stores visible
        unsigned old = atomicAdd(&g_grp[cb >> 4][0], 1u);
        if (((old + 1u) & 15u) == 0u) {
            unsigned ro = atomicAdd(&g_root[0], 1u);
            if (((ro + 1u) & 7u) == 0u)
                atomicAdd(&g_gen, 1u);
        }
        while ((int)(*(volatile unsigned*)&g_gen - target) < 0) { }
        __threadfence();                       // acquire
    }
    __syncthreads();
}

// ---------------- fp16 HMMA machinery ----------------
// SMEM layout (bytes):
#define OFF_W   0           // up to 64KB: [kc][4 nt][32 lane][2 u32] fp16 B-frags
#define OFF_Z   65536       // 64*33*4 = 8448
#define OFF_AUX 73984       // rec: hsb [64][8] fp16 (1KB); xg: bias[32] f32
#define OFF_BASE 75008      // unsigned: per-launch barrier epoch base
#define SMEM_REC 75264

// Pack this CTA's 32 gate columns of W (row stride KDIM) into fp16 B-fragments.
// Uses threads 0..255 (one-time cost).
template <int KDIM>
__device__ void pack_w(const float* __restrict__ w, char* smem, int cb, int tid) {
    if (tid >= 256) return;
    int nt = tid >> 6;            // 0..3
    int l  = (tid >> 1) & 31;
    int word = tid & 1;
    int j = nt * 8 + (l >> 2);    // local col 0..31
    int row = (j >> 3) * H + cb * 8 + (j & 7);
    const float* src = w + (size_t)row * KDIM;
#pragma unroll 4
    for (int kc = 0; kc < KDIM / 16; kc++) {
        int k0 = kc * 16 + (l & 3) * 2 + word * 8;
        u32 v = packhf(__ldg(src + k0), __ldg(src + k0 + 1));
        *(u32*)(smem + OFF_W + ((kc * 4 + nt) * 32 + l) * 8 + word * 4) = v;
    }
}

// 16-warp fp16 mainloop: warp w owns ONE (mt, nt) job = 64 dependent MMAs.
// A image: [64 rows x K] fp16 entries (kc, mt, lane). mt = w>>2, nt = w&3.
// 6-deep LDG ring hides L2 latency. Result -> Z[64][33] in SMEM.
template <int NKC, bool CG>
__device__ void mma_mainloop(const unsigned char* __restrict__ img, char* smem,
                             int wid, int lane) {
    const int mt = wid >> 2;
    const int nt = wid & 3;
    constexpr int PF = (NKC < 6) ? NKC : 6;

    float d[4];
#pragma unroll
    for (int p = 0; p < 4; p++) d[p] = 0.f;

    uint4 rb[8];
#pragma unroll
    for (int p = 0; p < PF; p++) rb[p] = ldimg<CG>(img, p, mt, lane);

#pragma unroll 8
    for (int kc = 0; kc < NKC; kc++) {
        uint4 a = rb[kc & 7];
        int pf = kc + PF;
        if (pf < NKC) rb[pf & 7] = ldimg<CG>(img, pf, mt, lane);
        uint2 b = *(const uint2*)(smem + OFF_W + ((size_t)(kc * 4 + nt) * 32 + lane) * 8);
        mma_f16(d, a, b.x, b.y);
    }

    float* Z = (float*)(smem + OFF_Z);
    const int g = lane >> 2, tq = lane & 3;
    const int c = nt * 8 + tq * 2;
    Z[(mt * 16 + g) * 33 + c]         = d[0];
    Z[(mt * 16 + g) * 33 + c + 1]     = d[1];
    Z[(mt * 16 + g + 8) * 33 + c]     = d[2];
    Z[(mt * 16 + g + 8) * 33 + c + 1] = d[3];
}

// ---------------- kernel: X [B][T][F] -> K=64 fp16 frag image (fused transpose) ---
__global__ void __launch_bounds__(256)
cvt1_kernel(const float* __restrict__ X) {
    __shared__ float xs[64][65];     // xs[f][b]
    int t = blockIdx.x, tid = threadIdx.x;
    unsigned char* out = &g_x1Img[(size_t)t * 8192];

    {
        int b = tid >> 2, fq = (tid & 3) * 16;
        const float4* s = (const float4*)(X + ((size_t)b * T + t) * F + fq);
#pragma unroll
        for (int m = 0; m < 4; m++) {
            float4 v = s[m];
            xs[fq + m * 4 + 0][b] = v.x; xs[fq + m * 4 + 1][b] = v.y;
            xs[fq + m * 4 + 2][b] = v.z; xs[fq + m * 4 + 3][b] = v.w;
        }
    }
    __syncthreads();
    for (int e = tid; e < 512; e += 256) {
        int lane = e & 31, mt = (e >> 5) & 3, kcL = e >> 7;   // kcL 0..3
        int k0 = kcL * 16 + (lane & 3) * 2;
        int r = mt * 16 + (lane >> 2);
        uint4 v;
        v.x = packhf(xs[k0][r],     xs[k0 + 1][r]);
        v.y = packhf(xs[k0][r + 8], xs[k0 + 1][r + 8]);
        v.z = packhf(xs[k0 + 8][r],     xs[k0 + 9][r]);
        v.w = packhf(xs[k0 + 8][r + 8], xs[k0 + 9][r + 8]);
        *(uint4*)(out + ioff(kcL, mt, lane)) = v;
    }
}

// ---------------- kernel: xg via fp16 HMMA (any K) ----------------
template <int KDIM>
__global__ void __launch_bounds__(NTHR, 1)
xg_mma_kernel(const float* __restrict__ w_ih, const float* __restrict__ b_ih,
              const float* __restrict__ b_hh, const unsigned char* __restrict__ imgbase,
              size_t tstride) {
    extern __shared__ char smem[];
    const int cb = blockIdx.x, tid = threadIdx.x;
    const int wid = tid >> 5, lane = tid & 31;

    pack_w<KDIM>(w_ih, smem, cb, tid);
    float* bias = (float*)(smem + OFF_AUX);
    if (tid < 32) {
        int cg = ((tid >> 3) * H) + cb * 8 + (tid & 7);
        bias[tid] = b_ih[cg] + b_hh[cg];
    }
    __syncthreads();

    float* Z = (float*)(smem + OFF_Z);
    const int colw = tid >> 4;            // 0..31
    const int b0w  = (tid & 15) * 4;      // 0..60
    const int cgw = ((colw >> 3) * H) + cb * 8 + (colw & 7);

    for (int t = 0; t < T; t++) {
        mma_mainloop<KDIM / 16, false>(imgbase + (size_t)t * tstride, smem, wid, lane);
        __syncthreads();

        float bsum = bias[colw];
        float4 s;
        s.x = Z[(b0w + 0) * 33 + colw] + bsum;
        s.y = Z[(b0w + 1) * 33 + colw] + bsum;
        s.z = Z[(b0w + 2) * 33 + colw] + bsum;
        s.w = Z[(b0w + 3) * 33 + colw] + bsum;
        *(float4*)(g_xg + ((size_t)t * G4H + cgw) * B + b0w) = s;
        __syncthreads();
    }
}

// ---------------- kernel: recurrent scan — fp16 HMMA, 512 thr, fused cvt ----------
__global__ void __launch_bounds__(NTHR, 1)
rec_kernel(const float* __restrict__ w_hh, float* __restrict__ hseq,
           unsigned char* __restrict__ xout /* next layer x image or null */) {
    extern __shared__ char smem[];
    const int cb = blockIdx.x, tid = threadIdx.x;
    const int wid = tid >> 5, lane = tid & 31;

    pack_w<H>(w_hh, smem, cb, tid);
    if (tid == 0) *(unsigned*)(smem + OFF_BASE) = *(volatile unsigned*)&g_gen;
    __syncthreads();
    const unsigned base = *(const unsigned*)(smem + OFF_BASE);

    float* Z = (float*)(smem + OFF_Z);
    __half* hsb = (__half*)(smem + OFF_AUX);     // [64 batch][8 unit]

    const int u = tid >> 6;          // local unit 0..7
    const int b = tid & 63;          // batch
    const int uglob = cb * 8 + u;
    float c = 0.f;

    for (int t = 0; t < T; t++) {
        float xg4[4];
#pragma unroll
        for (int g = 0; g < 4; g++)
            xg4[g] = __ldg(g_xg + ((size_t)t * G4H + g * H + uglob) * B + b);

        if (t > 0)
            mma_mainloop<64, true>(&g_hImg[(t - 1) & 1][0], smem, wid, lane);
        __syncthreads();

        float z[4];
#pragma unroll
        for (int g = 0; g < 4; g++)
            z[g] = (t > 0) ? (Z[b * 33 + g * 8 + u] + xg4[g]) : xg4[g];

        float ig = sigf(z[0]), fg = sigf(z[1]);
        float gg = tanhf_fast(z[2]), og = sigf(z[3]);
        c = fg * c + ig * gg;
        float h = og * tanhf_fast(c);

        hseq[((size_t)t * H + uglob) * B + b] = h;
        hsb[b * 8 + u] = __float2half_rn(h);
        __syncthreads();

        // publish fp16 image words: this CTA owns k = cb*8 .. cb*8+7
        if (tid < 256) {
            int r = tid >> 2, kp = tid & 3;
            u32 val = ((const u32*)hsb)[r * 4 + kp];
            u32 off = ioff(cb >> 1, r >> 4, (r & 7) * 4 + kp) +
                      (u32)(((cb & 1) * 2 + ((r >> 3) & 1)) * 4);
            *(u32*)(&g_hImg[t & 1][0] + off) = val;
            if (xout)   // fused cvt: same words feed next layer's x image
                *(u32*)(xout + ((size_t)t << 17) + off) = val;
        }
        grid_barrier_h(base + (unsigned)t + 1u, tid, cb);
    }
}

// ---------------- kernel: projection ----------------
__global__ void __launch_bounds__(256)
proj_kernel(const float* __restrict__ hseq, const float* __restrict__ w_out,
            const float* __restrict__ b_out, float* __restrict__ out) {
    __shared__ float Sh[64][68];
    __shared__ float Sw[64][68];
    int t = blockIdx.x, tid = threadIdx.x;
    int fg = tid >> 4, bg = tid & 15;
    float accv[4][4];
#pragma unroll
    for (int i = 0; i < 4; i++)
#pragma unroll
        for (int j = 0; j < 4; j++) accv[i][j] = 0.f;

    for (int kc = 0; kc < H; kc += 64) {
        __syncthreads();
        {
            int i = tid >> 2, b = (tid & 3) * 16;
            const float4* src = (const float4*)(hseq + ((size_t)t * H + kc + i) * B + b);
#pragma unroll
            for (int m = 0; m < 4; m++) {
                float4 v = src[m];
                Sh[i][b + m * 4 + 0] = v.x; Sh[i][b + m * 4 + 1] = v.y;
                Sh[i][b + m * 4 + 2] = v.z; Sh[i][b + m * 4 + 3] = v.w;
            }
        }
        {
            int f = tid >> 2, kk = (tid & 3) * 16;
            const float4* src = (const float4*)(w_out + (size_t)f * H + kc + kk);
#pragma unroll
            for (int m = 0; m < 4; m++) {
                float4 v = src[m];
                Sw[kk + m * 4 + 0][f] = v.x; Sw[kk + m * 4 + 1][f] = v.y;
                Sw[kk + m * 4 + 2][f] = v.z; Sw[kk + m * 4 + 3][f] = v.w;
            }
        }
        __syncthreads();
#pragma unroll 4
        for (int k = 0; k < 64; k++) {
            float4 wv = *(const float4*)&Sw[k][fg * 4];
            float4 hv = *(const float4*)&Sh[k][bg * 4];
            float wr[4] = {wv.x, wv.y, wv.z, wv.w};
            float hr[4] = {hv.x, hv.y, hv.z, hv.w};
#pragma unroll
            for (int i = 0; i < 4; i++)
#pragma unroll
                for (int j = 0; j < 4; j++) accv[i][j] += wr[i] * hr[j];
        }
    }
    int fbase = fg * 4, bbase = bg * 4;
#pragma unroll
    for (int j = 0; j < 4; j++) {
        int b = bbase + j;
        float4 r;
        r.x = tanhf(accv[0][j] + b_out[fbase + 0]);
        r.y = tanhf(accv[1][j] + b_out[fbase + 1]);
        r.z = tanhf(accv[2][j] + b_out[fbase + 2]);
        r.w = tanhf(accv[3][j] + b_out[fbase + 3]);
        *(float4*)(out + ((size_t)b * T + t) * F + fbase) = r;
    }
}

// ---------------- launch ----------------
extern "C" void kernel_launch(void* const* d_in, const int* in_sizes, int n_in,
                              void* d_out, int out_size) {
    const float* X = (const float*)d_in[0];
    const float* w_ih[3] = {(const float*)d_in[1], (const float*)d_in[5], (const float*)d_in[9]};
    const float* w_hh[3] = {(const float*)d_in[2], (const float*)d_in[6], (const float*)d_in[10]};
    const float* b_ih[3] = {(const float*)d_in[3], (const float*)d_in[7], (const float*)d_in[11]};
    const float* b_hh[3] = {(const float*)d_in[4], (const float*)d_in[8], (const float*)d_in[12]};
    const float* w_out = (const float*)d_in[13];
    const float* b_out = (const float*)d_in[14];
    float* out = (float*)d_out;

    float *aA = nullptr, *aB = nullptr;
    unsigned char *xImg = nullptr, *x1Img = nullptr;
    cudaGetSymbolAddress((void**)&aA, g_actA);
    cudaGetSymbolAddress((void**)&aB, g_actB);
    cudaGetSymbolAddress((void**)&xImg, g_xImg);
    cudaGetSymbolAddress((void**)&x1Img, g_x1Img);

    cudaFuncSetAttribute(rec_kernel, cudaFuncAttributeMaxDynamicSharedMemorySize, SMEM_REC);
    cudaFuncSetAttribute(xg_mma_kernel<64>, cudaFuncAttributeMaxDynamicSharedMemorySize, SMEM_REC);
    cudaFuncSetAttribute(xg_mma_kernel<H>, cudaFuncAttributeMaxDynamicSharedMemorySize, SMEM_REC);

    // layer 1 (K=64, image built straight from X)
    cvt1_kernel<<<T, 256>>>(X);
    xg_mma_kernel<64><<<NCTA, NTHR, SMEM_REC>>>(w_ih[0], b_ih[0], b_hh[0], x1Img, 8192);
    rec_kernel<<<NCTA, NTHR, SMEM_REC>>>(w_hh[0], aB, xImg);   // writes layer-2 x image

    // layer 2
    xg_mma_kernel<H><<<NCTA, NTHR, SMEM_REC>>>(w_ih[1], b_ih[1], b_hh[1], xImg, (size_t)1 << 17);
    rec_kernel<<<NCTA, NTHR, SMEM_REC>>>(w_hh[1], aA, xImg);   // writes layer-3 x image

    // layer 3
    xg_mma_kernel<H><<<NCTA, NTHR, SMEM_REC>>>(w_ih[2], b_ih[2], b_hh[2], xImg, (size_t)1 << 17);
    rec_kernel<<<NCTA, NTHR, SMEM_REC>>>(w_hh[2], aB, nullptr);

    proj_kernel<<<T, 256>>>(aB, w_out, b_out, out);
}

// round 13
// speedup vs baseline: 1.3209x; 1.3209x over previous
#include <cuda_runtime.h>
#include <cuda_fp16.h>
#include <math.h>

#define B 64
#define T 256
#define F 64
#define H 1024
#define G4H 4096
#define NCTA 128
#define NTHR 256

typedef unsigned long long ull;
typedef unsigned int u32;

// ---------------- scratch globals ----------------
__device__ __align__(256) float g_xg[(size_t)T * G4H * B];   // [T][4096][B]
__device__ __align__(256) float g_actA[(size_t)T * H * B];   // [T][H][B]
__device__ __align__(256) float g_actB[(size_t)T * H * B];   // [T][H][B]
// fp16 fragment images: entry (kc, mt, lane) -> 16B
__device__ __align__(256) unsigned char g_hImg[2][64 * 4 * 32 * 16];          // h image (128KB each)
__device__ __align__(256) unsigned char g_xImg[(size_t)T * 64 * 4 * 32 * 16]; // x image, K=1024 layers
__device__ __align__(256) unsigned char g_x1Img[(size_t)T * 4 * 4 * 32 * 16]; // x image, K=64 layer 1
// hierarchical barrier state (monotonic counters; no resets)
__device__ __align__(256) unsigned g_grp[8][64];   // one counter per 256B line
__device__ __align__(256) unsigned g_root[64];
__device__ __align__(256) unsigned g_gen;

// ---------------- helpers ----------------
__device__ __forceinline__ float sigf(float x) {
    return __fdividef(1.f, 1.f + __expf(-x));
}
// inf-safe fast tanh: 1 - 2/(e^{2x}+1)
__device__ __forceinline__ float tanhf_fast(float x) {
    return 1.f - __fdividef(2.f, __expf(2.f * x) + 1.f);
}

__device__ __forceinline__ u32 packhf(float a, float b) {
    __half2 h = __floats2half2_rn(a, b);
    return *(u32*)&h;
}

__device__ __forceinline__ void mma_f16(float* d, const uint4& a, u32 b0, u32 b1) {
    asm volatile(
        "mma.sync.aligned.m16n8k16.row.col.f32.f16.f16.f32 "
        "{%0,%1,%2,%3},{%4,%5,%6,%7},{%8,%9},{%0,%1,%2,%3};"
        : "+f"(d[0]), "+f"(d[1]), "+f"(d[2]), "+f"(d[3])
        : "r"(a.x), "r"(a.y), "r"(a.z), "r"(a.w), "r"(b0), "r"(b1));
}

__device__ __forceinline__ u32 ioff(int kc, int mt, int lane) {
    return (u32)(((kc * 4 + mt) * 32 + lane) << 4);
}
template <bool CG>
__device__ __forceinline__ uint4 ldimg(const unsigned char* img, int kc, int mt, int lane) {
    const uint4* p = (const uint4*)(img + ioff(kc, mt, lane));
    return CG ? __ldcg(p) : __ldg(p);
}

// Hierarchical grid barrier (proven R10): 16-way group -> 8-way root -> g_gen.
// Single polling thread per CTA. target = per-launch base + t + 1; wrap-safe.
__device__ __forceinline__ void grid_barrier_h(unsigned target, int tid, int cb) {
    __syncthreads();
    if (tid == 0) {
        __threadfence();                       // release: publish stores visible
        unsigned old = atomicAdd(&g_grp[cb >> 4][0], 1u);
        if (((old + 1u) & 15u) == 0u) {
            unsigned ro = atomicAdd(&g_root[0], 1u);
            if (((ro + 1u) & 7u) == 0u)
                atomicAdd(&g_gen, 1u);
        }
        while ((int)(*(volatile unsigned*)&g_gen - target) < 0) { }
        __threadfence();                       // acquire
    }
    __syncthreads();
}

// ---------------- fp16 HMMA machinery ----------------
// SMEM layout (bytes):
#define OFF_W    0          // up to 64KB: [kc][4 nt][32 lane][2 u32] fp16 B-frags
#define OFF_Z    65536      // k-half 0 partials: 64*33*4 = 8448
#define OFF_Z2   73984      // k-half 1 partials: 8448
#define OFF_AUX  82432      // rec: hsb [64][8] fp16 (1KB); xg: bias[32] f32
#define OFF_BASE 83456      // unsigned: per-launch barrier epoch base
#define SMEM_REC 83712

// Pack this CTA's 32 gate columns of W (row stride KDIM) into fp16 B-fragments.
template <int KDIM>
__device__ void pack_w(const float* __restrict__ w, char* smem, int cb, int tid) {
    int nt = tid >> 6;            // 0..3
    int l  = (tid >> 1) & 31;
    int word = tid & 1;
    int j = nt * 8 + (l >> 2);    // local col 0..31
    int row = (j >> 3) * H + cb * 8 + (j & 7);
    const float* src = w + (size_t)row * KDIM;
#pragma unroll 4
    for (int kc = 0; kc < KDIM / 16; kc++) {
        int k0 = kc * 16 + (l & 3) * 2 + word * 8;
        u32 v = packhf(__ldg(src + k0), __ldg(src + k0 + 1));
        *(u32*)(smem + OFF_W + ((kc * 4 + nt) * 32 + l) * 8 + word * 4) = v;
    }
}

// Zero-A-redundancy fp16 mainloop: 8 warps = 4 mt x 2 k-halves.
// Warp (mt, kh) loads its A fragment ONCE per kc and runs all 4 nt jobs on it
// (4 LDS.64 + 4 MMA). 32 kc per warp; partials -> Zhi (kh=0) / Zlo (kh=1).
template <int NKC, bool CG>
__device__ void mma_mainloop(const unsigned char* __restrict__ img, char* smem,
                             int wid, int lane) {
    const int mt = wid & 3;
    const int kh = wid >> 2;               // 0 or 1
    constexpr int HK = NKC / 2;
    constexpr int PF = (HK < 6) ? HK : 6;
    const int kc0 = kh * HK;

    float d[4][4];
#pragma unroll
    for (int n = 0; n < 4; n++)
#pragma unroll
        for (int p = 0; p < 4; p++) d[n][p] = 0.f;

    uint4 rb[8];
#pragma unroll
    for (int p = 0; p < PF; p++) rb[p] = ldimg<CG>(img, kc0 + p, mt, lane);

#pragma unroll 8
    for (int i = 0; i < HK; i++) {
        uint4 a = rb[i & 7];
        int pf = i + PF;
        if (pf < HK) rb[pf & 7] = ldimg<CG>(img, kc0 + pf, mt, lane);
        const int kc = kc0 + i;
#pragma unroll
        for (int nt = 0; nt < 4; nt++) {
            uint2 b = *(const uint2*)(smem + OFF_W + ((size_t)(kc * 4 + nt) * 32 + lane) * 8);
            mma_f16(d[nt], a, b.x, b.y);
        }
    }

    float* Z = (float*)(smem + (kh ? OFF_Z2 : OFF_Z));
    const int g = lane >> 2, tq = lane & 3;
#pragma unroll
    for (int nt = 0; nt < 4; nt++) {
        int c = nt * 8 + tq * 2;
        Z[(mt * 16 + g) * 33 + c]         = d[nt][0];
        Z[(mt * 16 + g) * 33 + c + 1]     = d[nt][1];
        Z[(mt * 16 + g + 8) * 33 + c]     = d[nt][2];
        Z[(mt * 16 + g + 8) * 33 + c + 1] = d[nt][3];
    }
}

// ---------------- kernel: X [B][T][F] -> K=64 fp16 frag image (fused transpose) ---
__global__ void __launch_bounds__(256)
cvt1_kernel(const float* __restrict__ X) {
    __shared__ float xs[64][65];     // xs[f][b]
    int t = blockIdx.x, tid = threadIdx.x;
    unsigned char* out = &g_x1Img[(size_t)t * 8192];

    {
        int b = tid >> 2, fq = (tid & 3) * 16;
        const float4* s = (const float4*)(X + ((size_t)b * T + t) * F + fq);
#pragma unroll
        for (int m = 0; m < 4; m++) {
            float4 v = s[m];
            xs[fq + m * 4 + 0][b] = v.x; xs[fq + m * 4 + 1][b] = v.y;
            xs[fq + m * 4 + 2][b] = v.z; xs[fq + m * 4 + 3][b] = v.w;
        }
    }
    __syncthreads();
    for (int e = tid; e < 512; e += 256) {
        int lane = e & 31, mt = (e >> 5) & 3, kcL = e >> 7;   // kcL 0..3
        int k0 = kcL * 16 + (lane & 3) * 2;
        int r = mt * 16 + (lane >> 2);
        uint4 v;
        v.x = packhf(xs[k0][r],     xs[k0 + 1][r]);
        v.y = packhf(xs[k0][r + 8], xs[k0 + 1][r + 8]);
        v.z = packhf(xs[k0 + 8][r],     xs[k0 + 9][r]);
        v.w = packhf(xs[k0 + 8][r + 8], xs[k0 + 9][r + 8]);
        *(uint4*)(out + ioff(kcL, mt, lane)) = v;
    }
}

// ---------------- kernel: xg via fp16 HMMA (any K) ----------------
template <int KDIM>
__global__ void __launch_bounds__(NTHR, 1)
xg_mma_kernel(const float* __restrict__ w_ih, const float* __restrict__ b_ih,
              const float* __restrict__ b_hh, const unsigned char* __restrict__ imgbase,
              size_t tstride) {
    extern __shared__ char smem[];
    const int cb = blockIdx.x, tid = threadIdx.x;
    const int wid = tid >> 5, lane = tid & 31;

    pack_w<KDIM>(w_ih, smem, cb, tid);
    float* bias = (float*)(smem + OFF_AUX);
    if (tid < 32) {
        int cg = ((tid >> 3) * H) + cb * 8 + (tid & 7);
        bias[tid] = b_ih[cg] + b_hh[cg];
    }
    __syncthreads();

    float* Zh = (float*)(smem + OFF_Z);
    float* Zl = (float*)(smem + OFF_Z2);
    const int colw = tid >> 3, b0w = (tid & 7) * 8;
    const int cgw = ((colw >> 3) * H) + cb * 8 + (colw & 7);

    for (int t = 0; t < T; t++) {
        mma_mainloop<KDIM / 16, false>(imgbase + (size_t)t * tstride, smem, wid, lane);
        __syncthreads();

        float bsum = bias[colw];
        float s[8];
#pragma unroll
        for (int i = 0; i < 8; i++) {
            int r = (b0w + i) * 33 + colw;
            s[i] = Zh[r] + Zl[r] + bsum;
        }
        float* dst = g_xg + ((size_t)t * G4H + cgw) * B + b0w;
        *(float4*)dst = make_float4(s[0], s[1], s[2], s[3]);
        *(float4*)(dst + 4) = make_float4(s[4], s[5], s[6], s[7]);
        __syncthreads();
    }
}

// ---------------- kernel: recurrent scan — fp16 HMMA, fused cvt -------------------
__global__ void __launch_bounds__(NTHR, 1)
rec_kernel(const float* __restrict__ w_hh, float* __restrict__ hseq,
           unsigned char* __restrict__ xout /* next layer x image or null */) {
    extern __shared__ char smem[];
    const int cb = blockIdx.x, tid = threadIdx.x;
    const int wid = tid >> 5, lane = tid & 31;

    pack_w<H>(w_hh, smem, cb, tid);
    if (tid == 0) *(unsigned*)(smem + OFF_BASE) = *(volatile unsigned*)&g_gen;
    __syncthreads();
    const unsigned base = *(const unsigned*)(smem + OFF_BASE);

    float* Zh = (float*)(smem + OFF_Z);
    float* Zl = (float*)(smem + OFF_Z2);
    __half* hsb = (__half*)(smem + OFF_AUX);     // [64 batch][8 unit]

    const int uglob = cb * 8 + wid;              // warp = unit
    const int b0 = lane * 2;                     // batch pair
    float c0 = 0.f, c1 = 0.f;

    for (int t = 0; t < T; t++) {
        float2 xgv[4];
#pragma unroll
        for (int g = 0; g < 4; g++)
            xgv[g] = __ldg((const float2*)(g_xg + ((size_t)t * G4H + g * H + uglob) * B + b0));

        if (t > 0)
            mma_mainloop<64, true>(&g_hImg[(t - 1) & 1][0], smem, wid, lane);
        __syncthreads();

        float z0[4], z1[4];
#pragma unroll
        for (int g = 0; g < 4; g++) {
            int j = g * 8 + wid;
            if (t > 0) {
                int r0 = b0 * 33 + j, r1 = (b0 + 1) * 33 + j;
                z0[g] = Zh[r0] + Zl[r0] + xgv[g].x;
                z1[g] = Zh[r1] + Zl[r1] + xgv[g].y;
            } else {
                z0[g] = xgv[g].x;
                z1[g] = xgv[g].y;
            }
        }
        float i0 = sigf(z0[0]), f0 = sigf(z0[1]);
        float gg0 = tanhf_fast(z0[2]), o0 = sigf(z0[3]);
        float i1 = sigf(z1[0]), f1 = sigf(z1[1]);
        float gg1 = tanhf_fast(z1[2]), o1 = sigf(z1[3]);
        c0 = f0 * c0 + i0 * gg0;
        c1 = f1 * c1 + i1 * gg1;
        float h0 = o0 * tanhf_fast(c0);
        float h1 = o1 * tanhf_fast(c1);

        *(float2*)(hseq + ((size_t)t * H + uglob) * B + b0) = make_float2(h0, h1);

        hsb[b0 * 8 + wid] = __float2half_rn(h0);
        hsb[(b0 + 1) * 8 + wid] = __float2half_rn(h1);
        __syncthreads();

        // publish fp16 image words: this CTA owns k = cb*8 .. cb*8+7
        {
            int r = tid >> 2, kp = tid & 3;
            u32 val = ((const u32*)hsb)[r * 4 + kp];
            u32 off = ioff(cb >> 1, r >> 4, (r & 7) * 4 + kp) +
                      (u32)(((cb & 1) * 2 + ((r >> 3) & 1)) * 4);
            *(u32*)(&g_hImg[t & 1][0] + off) = val;
            if (xout)   // fused cvt: same words feed next layer's x image
                *(u32*)(xout + ((size_t)t << 17) + off) = val;
        }
        grid_barrier_h(base + (unsigned)t + 1u, tid, cb);
    }
}

// ---------------- kernel: projection ----------------
__global__ void __launch_bounds__(256)
proj_kernel(const float* __restrict__ hseq, const float* __restrict__ w_out,
            const float* __restrict__ b_out, float* __restrict__ out) {
    __shared__ float Sh[64][68];
    __shared__ float Sw[64][68];
    int t = blockIdx.x, tid = threadIdx.x;
    int fg = tid >> 4, bg = tid & 15;
    float accv[4][4];
#pragma unroll
    for (int i = 0; i < 4; i++)
#pragma unroll
        for (int j = 0; j < 4; j++) accv[i][j] = 0.f;

    for (int kc = 0; kc < H; kc += 64) {
        __syncthreads();
        {
            int i = tid >> 2, b = (tid & 3) * 16;
            const float4* src = (const float4*)(hseq + ((size_t)t * H + kc + i) * B + b);
#pragma unroll
            for (int m = 0; m < 4; m++) {
                float4 v = src[m];
                Sh[i][b + m * 4 + 0] = v.x; Sh[i][b + m * 4 + 1] = v.y;
                Sh[i][b + m * 4 + 2] = v.z; Sh[i][b + m * 4 + 3] = v.w;
            }
        }
        {
            int f = tid >> 2, kk = (tid & 3) * 16;
            const float4* src = (const float4*)(w_out + (size_t)f * H + kc + kk);
#pragma unroll
            for (int m = 0; m < 4; m++) {
                float4 v = src[m];
                Sw[kk + m * 4 + 0][f] = v.x; Sw[kk + m * 4 + 1][f] = v.y;
                Sw[kk + m * 4 + 2][f] = v.z; Sw[kk + m * 4 + 3][f] = v.w;
            }
        }
        __syncthreads();
#pragma unroll 4
        for (int k = 0; k < 64; k++) {
            float4 wv = *(const float4*)&Sw[k][fg * 4];
            float4 hv = *(const float4*)&Sh[k][bg * 4];
            float wr[4] = {wv.x, wv.y, wv.z, wv.w};
            float hr[4] = {hv.x, hv.y, hv.z, hv.w};
#pragma unroll
            for (int i = 0; i < 4; i++)
#pragma unroll
                for (int j = 0; j < 4; j++) accv[i][j] += wr[i] * hr[j];
        }
    }
    int fbase = fg * 4, bbase = bg * 4;
#pragma unroll
    for (int j = 0; j < 4; j++) {
        int b = bbase + j;
        float4 r;
        r.x = tanhf(accv[0][j] + b_out[fbase + 0]);
        r.y = tanhf(accv[1][j] + b_out[fbase + 1]);
        r.z = tanhf(accv[2][j] + b_out[fbase + 2]);
        r.w = tanhf(accv[3][j] + b_out[fbase + 3]);
        *(float4*)(out + ((size_t)b * T + t) * F + fbase) = r;
    }
}

// ---------------- launch ----------------
extern "C" void kernel_launch(void* const* d_in, const int* in_sizes, int n_in,
                              void* d_out, int out_size) {
    const float* X = (const float*)d_in[0];
    const float* w_ih[3] = {(const float*)d_in[1], (const float*)d_in[5], (const float*)d_in[9]};
    const float* w_hh[3] = {(const float*)d_in[2], (const float*)d_in[6], (const float*)d_in[10]};
    const float* b_ih[3] = {(const float*)d_in[3], (const float*)d_in[7], (const float*)d_in[11]};
    const float* b_hh[3] = {(const float*)d_in[4], (const float*)d_in[8], (const float*)d_in[12]};
    const float* w_out = (const float*)d_in[13];
    const float* b_out = (const float*)d_in[14];
    float* out = (float*)d_out;

    float *aA = nullptr, *aB = nullptr;
    unsigned char *xImg = nullptr, *x1Img = nullptr;
    cudaGetSymbolAddress((void**)&aA, g_actA);
    cudaGetSymbolAddress((void**)&aB, g_actB);
    cudaGetSymbolAddress((void**)&xImg, g_xImg);
    cudaGetSymbolAddress((void**)&x1Img, g_x1Img);

    cudaFuncSetAttribute(rec_kernel, cudaFuncAttributeMaxDynamicSharedMemorySize, SMEM_REC);
    cudaFuncSetAttribute(xg_mma_kernel<64>, cudaFuncAttributeMaxDynamicSharedMemorySize, SMEM_REC);
    cudaFuncSetAttribute(xg_mma_kernel<H>, cudaFuncAttributeMaxDynamicSharedMemorySize, SMEM_REC);

    // layer 1 (K=64, image built straight from X)
    cvt1_kernel<<<T, 256>>>(X);
    xg_mma_kernel<64><<<NCTA, NTHR, SMEM_REC>>>(w_ih[0], b_ih[0], b_hh[0], x1Img, 8192);
    rec_kernel<<<NCTA, NTHR, SMEM_REC>>>(w_hh[0], aB, xImg);   // writes layer-2 x image

    // layer 2
    xg_mma_kernel<H><<<NCTA, NTHR, SMEM_REC>>>(w_ih[1], b_ih[1], b_hh[1], xImg, (size_t)1 << 17);
    rec_kernel<<<NCTA, NTHR, SMEM_REC>>>(w_hh[1], aA, xImg);   // writes layer-3 x image

    // layer 3
    xg_mma_kernel<H><<<NCTA, NTHR, SMEM_REC>>>(w_ih[2], b_ih[2], b_hh[2], xImg, (size_t)1 << 17);
    rec_kernel<<<NCTA, NTHR, SMEM_REC>>>(w_hh[2], aB, nullptr);

    proj_kernel<<<T, 256>>>(aB, w_out, b_out, out);
}

// round 14
// speedup vs baseline: 1.4309x; 1.0832x over previous
#include <cuda_runtime.h>
#include <cuda_fp16.h>
#include <math.h>

#define B 64
#define T 256
#define F 64
#define H 1024
#define G4H 4096
#define NCTA 128
#define NTHR 512

typedef unsigned long long ull;
typedef unsigned int u32;

// ---------------- scratch globals ----------------
__device__ __align__(256) float g_xg[(size_t)T * G4H * B];   // [T][4096][B]
__device__ __align__(256) float g_actA[(size_t)T * H * B];   // [T][H][B]
__device__ __align__(256) float g_actB[(size_t)T * H * B];   // [T][H][B]
// fp16 fragment images: entry (kc, mt, lane) -> 16B
__device__ __align__(256) unsigned char g_hImg[2][64 * 4 * 32 * 16];          // h image (128KB each)
__device__ __align__(256) unsigned char g_xImg[(size_t)T * 64 * 4 * 32 * 16]; // x image, K=1024 layers
__device__ __align__(256) unsigned char g_x1Img[(size_t)T * 4 * 4 * 32 * 16]; // x image, K=64 layer 1
// hierarchical barrier state (monotonic counters; no resets)
__device__ __align__(256) unsigned g_grp[8][64];   // one counter per 256B line
__device__ __align__(256) unsigned g_root[64];
__device__ __align__(256) unsigned g_gen;

// ---------------- helpers ----------------
__device__ __forceinline__ float sigf(float x) {
    return __fdividef(1.f, 1.f + __expf(-x));
}
// inf-safe fast tanh: 1 - 2/(e^{2x}+1)
__device__ __forceinline__ float tanhf_fast(float x) {
    return 1.f - __fdividef(2.f, __expf(2.f * x) + 1.f);
}

__device__ __forceinline__ u32 packhf(float a, float b) {
    __half2 h = __floats2half2_rn(a, b);
    return *(u32*)&h;
}

__device__ __forceinline__ void mma_f16(float* d, const uint4& a, u32 b0, u32 b1) {
    asm volatile(
        "mma.sync.aligned.m16n8k16.row.col.f32.f16.f16.f32 "
        "{%0,%1,%2,%3},{%4,%5,%6,%7},{%8,%9},{%0,%1,%2,%3};"
        : "+f"(d[0]), "+f"(d[1]), "+f"(d[2]), "+f"(d[3])
        : "r"(a.x), "r"(a.y), "r"(a.z), "r"(a.w), "r"(b0), "r"(b1));
}

__device__ __forceinline__ u32 ioff(int kc, int mt, int lane) {
    return (u32)(((kc * 4 + mt) * 32 + lane) << 4);
}
template <bool CG>
__device__ __forceinline__ uint4 ldimg(const unsigned char* img, int kc, int mt, int lane) {
    const uint4* p = (const uint4*)(img + ioff(kc, mt, lane));
    return CG ? __ldcg(p) : __ldg(p);
}

// Hierarchical grid barrier (proven R10): 16-way group -> 8-way root -> g_gen.
// Single polling thread per CTA. target = per-launch base + t + 1; wrap-safe.
__device__ __forceinline__ void grid_barrier_h(unsigned target, int tid, int cb) {
    __syncthreads();
    if (tid == 0) {
        __threadfence();                       // release: publish stores visible
        unsigned old = atomicAdd(&g_grp[cb >> 4][0], 1u);
        if (((old + 1u) & 15u) == 0u) {
            unsigned ro = atomicAdd(&g_root[0], 1u);
            if (((ro + 1u) & 7u) == 0u)
                atomicAdd(&g_gen, 1u);
        }
        while ((int)(*(volatile unsigned*)&g_gen - target) < 0) { }
        __threadfence();                       // acquire
    }
    __syncthreads();
}

// ---------------- fp16 HMMA machinery ----------------
// SMEM layout (bytes):
#define OFF_W    0          // up to 64KB: [kc][4 nt][32 lane][2 u32] fp16 B-frags
#define OFF_Z    65536      // 4 partial buffers, one per k-quarter
#define ZSTRIDE  8448       // 64*33*4
#define OFF_AUX  99328      // rec: hsb [64][8] fp16 (1KB); xg: bias[32] f32
#define OFF_BASE 100352     // unsigned: per-launch barrier epoch base
#define SMEM_REC 100608

// Pack this CTA's 32 gate columns of W (row stride KDIM) into fp16 B-fragments.
// Uses threads 0..255.
template <int KDIM>
__device__ void pack_w(const float* __restrict__ w, char* smem, int cb, int tid) {
    if (tid >= 256) return;
    int nt = tid >> 6;            // 0..3
    int l  = (tid >> 1) & 31;
    int word = tid & 1;
    int j = nt * 8 + (l >> 2);    // local col 0..31
    int row = (j >> 3) * H + cb * 8 + (j & 7);
    const float* src = w + (size_t)row * KDIM;
#pragma unroll 4
    for (int kc = 0; kc < KDIM / 16; kc++) {
        int k0 = kc * 16 + (l & 3) * 2 + word * 8;
        u32 v = packhf(__ldg(src + k0), __ldg(src + k0 + 1));
        *(u32*)(smem + OFF_W + ((kc * 4 + nt) * 32 + l) * 8 + word * 4) = v;
    }
}

// Zero-A-redundancy fp16 mainloop, 16 warps = 4 mt x 4 k-quarters.
// Warp (mt, kq) loads its A fragment ONCE per kc and runs all 4 nt jobs on it
// (4 LDS.64 + 4 MMA). NKC/4 kc per warp; partials -> Z[kq].
template <int NKC, bool CG>
__device__ void mma_mainloop(const unsigned char* __restrict__ img, char* smem,
                             int wid, int lane) {
    const int mt = wid & 3;
    const int kq = wid >> 2;               // 0..3
    constexpr int QK = NKC / 4;
    constexpr int PF = (QK < 6) ? QK : 6;
    const int kc0 = kq * QK;

    float d[4][4];
#pragma unroll
    for (int n = 0; n < 4; n++)
#pragma unroll
        for (int p = 0; p < 4; p++) d[n][p] = 0.f;

    uint4 rb[8];
#pragma unroll
    for (int p = 0; p < PF; p++) rb[p] = ldimg<CG>(img, kc0 + p, mt, lane);

#pragma unroll 8
    for (int i = 0; i < QK; i++) {
        uint4 a = rb[i & 7];
        int pf = i + PF;
        if (pf < QK) rb[pf & 7] = ldimg<CG>(img, kc0 + pf, mt, lane);
        const int kc = kc0 + i;
#pragma unroll
        for (int nt = 0; nt < 4; nt++) {
            uint2 b = *(const uint2*)(smem + OFF_W + ((size_t)(kc * 4 + nt) * 32 + lane) * 8);
            mma_f16(d[nt], a, b.x, b.y);
        }
    }

    float* Z = (float*)(smem + OFF_Z + kq * ZSTRIDE);
    const int g = lane >> 2, tq = lane & 3;
#pragma unroll
    for (int nt = 0; nt < 4; nt++) {
        int c = nt * 8 + tq * 2;
        Z[(mt * 16 + g) * 33 + c]         = d[nt][0];
        Z[(mt * 16 + g) * 33 + c + 1]     = d[nt][1];
        Z[(mt * 16 + g + 8) * 33 + c]     = d[nt][2];
        Z[(mt * 16 + g + 8) * 33 + c + 1] = d[nt][3];
    }
}

// ---------------- kernel: X [B][T][F] -> K=64 fp16 frag image (fused transpose) ---
__global__ void __launch_bounds__(256)
cvt1_kernel(const float* __restrict__ X) {
    __shared__ float xs[64][65];     // xs[f][b]
    int t = blockIdx.x, tid = threadIdx.x;
    unsigned char* out = &g_x1Img[(size_t)t * 8192];

    {
        int b = tid >> 2, fq = (tid & 3) * 16;
        const float4* s = (const float4*)(X + ((size_t)b * T + t) * F + fq);
#pragma unroll
        for (int m = 0; m < 4; m++) {
            float4 v = s[m];
            xs[fq + m * 4 + 0][b] = v.x; xs[fq + m * 4 + 1][b] = v.y;
            xs[fq + m * 4 + 2][b] = v.z; xs[fq + m * 4 + 3][b] = v.w;
        }
    }
    __syncthreads();
    for (int e = tid; e < 512; e += 256) {
        int lane = e & 31, mt = (e >> 5) & 3, kcL = e >> 7;   // kcL 0..3
        int k0 = kcL * 16 + (lane & 3) * 2;
        int r = mt * 16 + (lane >> 2);
        uint4 v;
        v.x = packhf(xs[k0][r],     xs[k0 + 1][r]);
        v.y = packhf(xs[k0][r + 8], xs[k0 + 1][r + 8]);
        v.z = packhf(xs[k0 + 8][r],     xs[k0 + 9][r]);
        v.w = packhf(xs[k0 + 8][r + 8], xs[k0 + 9][r + 8]);
        *(uint4*)(out + ioff(kcL, mt, lane)) = v;
    }
}

// ---------------- kernel: xg via fp16 HMMA (any K) ----------------
template <int KDIM>
__global__ void __launch_bounds__(NTHR, 1)
xg_mma_kernel(const float* __restrict__ w_ih, const float* __restrict__ b_ih,
              const float* __restrict__ b_hh, const unsigned char* __restrict__ imgbase,
              size_t tstride) {
    extern __shared__ char smem[];
    const int cb = blockIdx.x, tid = threadIdx.x;
    const int wid = tid >> 5, lane = tid & 31;

    pack_w<KDIM>(w_ih, smem, cb, tid);
    float* bias = (float*)(smem + OFF_AUX);
    if (tid < 32) {
        int cg = ((tid >> 3) * H) + cb * 8 + (tid & 7);
        bias[tid] = b_ih[cg] + b_hh[cg];
    }
    __syncthreads();

    float* Z0 = (float*)(smem + OFF_Z);
    float* Z1 = (float*)(smem + OFF_Z + ZSTRIDE);
    float* Z2 = (float*)(smem + OFF_Z + 2 * ZSTRIDE);
    float* Z3 = (float*)(smem + OFF_Z + 3 * ZSTRIDE);
    const int colw = tid >> 4;            // 0..31
    const int b0w  = (tid & 15) * 4;      // 0..60
    const int cgw = ((colw >> 3) * H) + cb * 8 + (colw & 7);

    for (int t = 0; t < T; t++) {
        mma_mainloop<KDIM / 16, false>(imgbase + (size_t)t * tstride, smem, wid, lane);
        __syncthreads();

        float bsum = bias[colw];
        float4 s;
        {
            int r0 = (b0w + 0) * 33 + colw, r1 = (b0w + 1) * 33 + colw;
            int r2 = (b0w + 2) * 33 + colw, r3 = (b0w + 3) * 33 + colw;
            s.x = Z0[r0] + Z1[r0] + Z2[r0] + Z3[r0] + bsum;
            s.y = Z0[r1] + Z1[r1] + Z2[r1] + Z3[r1] + bsum;
            s.z = Z0[r2] + Z1[r2] + Z2[r2] + Z3[r2] + bsum;
            s.w = Z0[r3] + Z1[r3] + Z2[r3] + Z3[r3] + bsum;
        }
        *(float4*)(g_xg + ((size_t)t * G4H + cgw) * B + b0w) = s;
        __syncthreads();
    }
}

// ---------------- kernel: recurrent scan — fp16 HMMA, 512 thr, fused cvt ----------
__global__ void __launch_bounds__(NTHR, 1)
rec_kernel(const float* __restrict__ w_hh, float* __restrict__ hseq,
           unsigned char* __restrict__ xout /* next layer x image or null */) {
    extern __shared__ char smem[];
    const int cb = blockIdx.x, tid = threadIdx.x;
    const int wid = tid >> 5, lane = tid & 31;

    pack_w<H>(w_hh, smem, cb, tid);
    if (tid == 0) *(unsigned*)(smem + OFF_BASE) = *(volatile unsigned*)&g_gen;
    __syncthreads();
    const unsigned base = *(const unsigned*)(smem + OFF_BASE);

    float* Z0 = (float*)(smem + OFF_Z);
    float* Z1 = (float*)(smem + OFF_Z + ZSTRIDE);
    float* Z2 = (float*)(smem + OFF_Z + 2 * ZSTRIDE);
    float* Z3 = (float*)(smem + OFF_Z + 3 * ZSTRIDE);
    __half* hsb = (__half*)(smem + OFF_AUX);     // [64 batch][8 unit]

    const int u = tid >> 6;          // local unit 0..7
    const int b = tid & 63;          // batch
    const int uglob = cb * 8 + u;
    float c = 0.f;

    for (int t = 0; t < T; t++) {
        float xg4[4];
#pragma unroll
        for (int g = 0; g < 4; g++)
            xg4[g] = __ldg(g_xg + ((size_t)t * G4H + g * H + uglob) * B + b);

        if (t > 0)
            mma_mainloop<64, true>(&g_hImg[(t - 1) & 1][0], smem, wid, lane);
        __syncthreads();

        float z[4];
#pragma unroll
        for (int g = 0; g < 4; g++) {
            if (t > 0) {
                int r = b * 33 + g * 8 + u;
                z[g] = Z0[r] + Z1[r] + Z2[r] + Z3[r] + xg4[g];
            } else {
                z[g] = xg4[g];
            }
        }

        float ig = sigf(z[0]), fg = sigf(z[1]);
        float gg = tanhf_fast(z[2]), og = sigf(z[3]);
        c = fg * c + ig * gg;
        float h = og * tanhf_fast(c);

        hseq[((size_t)t * H + uglob) * B + b] = h;
        hsb[b * 8 + u] = __float2half_rn(h);
        __syncthreads();

        // publish fp16 image words: this CTA owns k = cb*8 .. cb*8+7
        if (tid < 256) {
            int r = tid >> 2, kp = tid & 3;
            u32 val = ((const u32*)hsb)[r * 4 + kp];
            u32 off = ioff(cb >> 1, r >> 4, (r & 7) * 4 + kp) +
                      (u32)(((cb & 1) * 2 + ((r >> 3) & 1)) * 4);
            *(u32*)(&g_hImg[t & 1][0] + off) = val;
            if (xout)   // fused cvt: same words feed next layer's x image
                *(u32*)(xout + ((size_t)t << 17) + off) = val;
        }
        grid_barrier_h(base + (unsigned)t + 1u, tid, cb);
    }
}

// ---------------- kernel: projection ----------------
__global__ void __launch_bounds__(256)
proj_kernel(const float* __restrict__ hseq, const float* __restrict__ w_out,
            const float* __restrict__ b_out, float* __restrict__ out) {
    __shared__ float Sh[64][68];
    __shared__ float Sw[64][68];
    int t = blockIdx.x, tid = threadIdx.x;
    int fg = tid >> 4, bg = tid & 15;
    float accv[4][4];
#pragma unroll
    for (int i = 0; i < 4; i++)
#pragma unroll
        for (int j = 0; j < 4; j++) accv[i][j] = 0.f;

    for (int kc = 0; kc < H; kc += 64) {
        __syncthreads();
        {
            int i = tid >> 2, b = (tid & 3) * 16;
            const float4* src = (const float4*)(hseq + ((size_t)t * H + kc + i) * B + b);
#pragma unroll
            for (int m = 0; m < 4; m++) {
                float4 v = src[m];
                Sh[i][b + m * 4 + 0] = v.x; Sh[i][b + m * 4 + 1] = v.y;
                Sh[i][b + m * 4 + 2] = v.z; Sh[i][b + m * 4 + 3] = v.w;
            }
        }
        {
            int f = tid >> 2, kk = (tid & 3) * 16;
            const float4* src = (const float4*)(w_out + (size_t)f * H + kc + kk);
#pragma unroll
            for (int m = 0; m < 4; m++) {
                float4 v = src[m];
                Sw[kk + m * 4 + 0][f] = v.x; Sw[kk + m * 4 + 1][f] = v.y;
                Sw[kk + m * 4 + 2][f] = v.z; Sw[kk + m * 4 + 3][f] = v.w;
            }
        }
        __syncthreads();
#pragma unroll 4
        for (int k = 0; k < 64; k++) {
            float4 wv = *(const float4*)&Sw[k][fg * 4];
            float4 hv = *(const float4*)&Sh[k][bg * 4];
            float wr[4] = {wv.x, wv.y, wv.z, wv.w};
            float hr[4] = {hv.x, hv.y, hv.z, hv.w};
#pragma unroll
            for (int i = 0; i < 4; i++)
#pragma unroll
                for (int j = 0; j < 4; j++) accv[i][j] += wr[i] * hr[j];
        }
    }
    int fbase = fg * 4, bbase = bg * 4;
#pragma unroll
    for (int j = 0; j < 4; j++) {
        int b = bbase + j;
        float4 r;
        r.x = tanhf(accv[0][j] + b_out[fbase + 0]);
        r.y = tanhf(accv[1][j] + b_out[fbase + 1]);
        r.z = tanhf(accv[2][j] + b_out[fbase + 2]);
        r.w = tanhf(accv[3][j] + b_out[fbase + 3]);
        *(float4*)(out + ((size_t)b * T + t) * F + fbase) = r;
    }
}

// ---------------- launch ----------------
extern "C" void kernel_launch(void* const* d_in, const int* in_sizes, int n_in,
                              void* d_out, int out_size) {
    const float* X = (const float*)d_in[0];
    const float* w_ih[3] = {(const float*)d_in[1], (const float*)d_in[5], (const float*)d_in[9]};
    const float* w_hh[3] = {(const float*)d_in[2], (const float*)d_in[6], (const float*)d_in[10]};
    const float* b_ih[3] = {(const float*)d_in[3], (const float*)d_in[7], (const float*)d_in[11]};
    const float* b_hh[3] = {(const float*)d_in[4], (const float*)d_in[8], (const float*)d_in[12]};
    const float* w_out = (const float*)d_in[13];
    const float* b_out = (const float*)d_in[14];
    float* out = (float*)d_out;

    float *aA = nullptr, *aB = nullptr;
    unsigned char *xImg = nullptr, *x1Img = nullptr;
    cudaGetSymbolAddress((void**)&aA, g_actA);
    cudaGetSymbolAddress((void**)&aB, g_actB);
    cudaGetSymbolAddress((void**)&xImg, g_xImg);
    cudaGetSymbolAddress((void**)&x1Img, g_x1Img);

    cudaFuncSetAttribute(rec_kernel, cudaFuncAttributeMaxDynamicSharedMemorySize, SMEM_REC);
    cudaFuncSetAttribute(xg_mma_kernel<64>, cudaFuncAttributeMaxDynamicSharedMemorySize, SMEM_REC);
    cudaFuncSetAttribute(xg_mma_kernel<H>, cudaFuncAttributeMaxDynamicSharedMemorySize, SMEM_REC);

    // layer 1 (K=64, image built straight from X)
    cvt1_kernel<<<T, 256>>>(X);
    xg_mma_kernel<64><<<NCTA, NTHR, SMEM_REC>>>(w_ih[0], b_ih[0], b_hh[0], x1Img, 8192);
    rec_kernel<<<NCTA, NTHR, SMEM_REC>>>(w_hh[0], aB, xImg);   // writes layer-2 x image

    // layer 2
    xg_mma_kernel<H><<<NCTA, NTHR, SMEM_REC>>>(w_ih[1], b_ih[1], b_hh[1], xImg, (size_t)1 << 17);
    rec_kernel<<<NCTA, NTHR, SMEM_REC>>>(w_hh[1], aA, xImg);   // writes layer-3 x image

    // layer 3
    xg_mma_kernel<H><<<NCTA, NTHR, SMEM_REC>>>(w_ih[2], b_ih[2], b_hh[2], xImg, (size_t)1 << 17);
    rec_kernel<<<NCTA, NTHR, SMEM_REC>>>(w_hh[2], aB, nullptr);

    proj_kernel<<<T, 256>>>(aB, w_out, b_out, out);
}